// round 3
// baseline (speedup 1.0000x reference)
#include <cuda_runtime.h>
#include <math.h>

#define MAX_T 65536
#define JW 10
#define DCH 100          // days per chunk (T=50000 -> 500 chunks)
#define SEG (DCH / 2)    // days per prep-thread (50) -> anchors land on even threads

// Scratch (allocation-free rule: __device__ globals)
__device__ float g_logr[MAX_T];
__device__ float g_Pex[1024];   // exclusive prefix of logr at chunk starts

typedef unsigned long long u64;

// ---- packed f32x2 helpers (sm_103a) ----
__device__ __forceinline__ u64 pk2(float lo, float hi) {
    u64 r; asm("mov.b64 %0, {%1, %2};" : "=l"(r) : "f"(lo), "f"(hi)); return r;
}
__device__ __forceinline__ u64 mul2(u64 a, u64 b) {
    u64 d; asm("mul.rn.f32x2 %0, %1, %2;" : "=l"(d) : "l"(a), "l"(b)); return d;
}
__device__ __forceinline__ u64 fma2(u64 a, u64 b, u64 c) {
    u64 d; asm("fma.rn.f32x2 %0, %1, %2, %3;" : "=l"(d) : "l"(a), "l"(b), "l"(c)); return d;
}
__device__ __forceinline__ u64 add2(u64 a, u64 b) {
    u64 d; asm("add.rn.f32x2 %0, %1, %2;" : "=l"(d) : "l"(a), "l"(b)); return d;
}
__device__ __forceinline__ void stcs64(u64* p, u64 v) {
    asm volatile("st.global.cs.b64 [%0], %1;" :: "l"(p), "l"(v) : "memory");
}

// log(1+x), |x| <= ~0.011: degree-5, trunc err ~2e-13, fp32 rounding ~1e-9 abs
__device__ __forceinline__ float log1p_poly(float x) {
    float p = fmaf(x, 0.2f, -0.25f);
    p = fmaf(x, p, 1.0f / 3.0f);
    p = fmaf(x, p, -0.5f);
    p = fmaf(x, p, 1.0f);
    return x * p;
}

// ---- fused prep: log(r) -> g_logr, and chunk-start exclusive prefixes -> g_Pex
// Single block, 1024 threads; thread t owns days [t*SEG, t*SEG+SEG).
// Chunk c's anchor (day c*DCH) is the segment start of thread 2c, so the
// anchor value is exactly that thread's exclusive block-scan prefix.
__global__ void __launch_bounds__(1024) prep_kernel(const float* __restrict__ r,
                                                    int T, int nch) {
    __shared__ double sh[1024];
    int t = threadIdx.x;
    int beg = t * SEG;

    double a0 = 0.0, a1 = 0.0, a2 = 0.0, a3 = 0.0;
    if (beg < T) {
        int end = min(beg + SEG, T);
        int i = beg;
        // beg*4B is 200B-aligned -> 8B-aligned: use float2
        for (; i + 2 <= end; i += 2) {
            float2 rv = *(const float2*)(r + i);
            float l0 = log1p_poly(rv.x - 1.0f);
            float l1 = log1p_poly(rv.y - 1.0f);
            g_logr[i] = l0;
            g_logr[i + 1] = l1;
            if ((i & 2) == 0) { a0 += (double)l0; a1 += (double)l1; }
            else              { a2 += (double)l0; a3 += (double)l1; }
        }
        for (; i < end; ++i) {
            float l0 = log1p_poly(r[i] - 1.0f);
            g_logr[i] = l0;
            a0 += (double)l0;
        }
    }
    double loc = (a0 + a2) + (a1 + a3);
    sh[t] = loc;
    __syncthreads();
    // Hillis-Steele inclusive scan over 1024 partials
#pragma unroll
    for (int off = 1; off < 1024; off <<= 1) {
        double v = (t >= off) ? sh[t - off] : 0.0;
        __syncthreads();
        sh[t] += v;
        __syncthreads();
    }
    // exclusive prefix at this thread's segment start
    if ((t & 1) == 0) {
        int c = t >> 1;
        if (c < nch) g_Pex[c] = (float)(sh[t] - loc);
    }
}

// ---- main kernel ----
// A[d,s] = wlast[s]*exp(P[d]*invT[s]); chunk anchored exactly via g_Pex,
// in-chunk recurrence uses degree-3 poly for exp(logr*invT) (|x|<=0.0035).
// M[d,s] = sum_j (rho*pi[j,s]) * A_ext[J+d-1-j, s]
__global__ void __launch_bounds__(128) main_kernel(
    const float* __restrict__ warm,   // (J,S)
    const float* __restrict__ Ts,     // (S,)
    const float* __restrict__ rho,    // (S,)
    const float* __restrict__ pi,     // (J,S)
    u64* __restrict__ out,            // (T, S/2) packed float2
    int T, int S)
{
    int p = blockIdx.x * blockDim.x + threadIdx.x;
    int npairs = S >> 1;
    if (p >= npairs) return;
    int c  = blockIdx.y;
    int d0 = c * DCH;
    int s0 = 2 * p;

    float invT0 = 1.0f / Ts[s0];
    float invT1 = 1.0f / Ts[s0 + 1];
    float rho0 = rho[s0], rho1 = rho[s0 + 1];
    float wl0 = warm[(JW - 1) * S + s0];
    float wl1 = warm[(JW - 1) * S + s0 + 1];

    // dot weights with rho folded in
    u64 pir[JW];
#pragma unroll
    for (int j = 0; j < JW; ++j)
        pir[j] = pk2(pi[j * S + s0] * rho0, pi[j * S + s0 + 1] * rho1);

    // window init: win[j] = A_ext[J + d0 - 1 - j]
    u64 win[JW];
    if (c == 0) {
#pragma unroll
        for (int j = 0; j < JW; ++j)
            win[j] = pk2(warm[(JW - 1 - j) * S + s0],
                         warm[(JW - 1 - j) * S + s0 + 1]);
    } else {
        float Pex = g_Pex[c];                 // sum logr[0..d0-1]
        win[0] = pk2(wl0 * expf(Pex * invT0), wl1 * expf(Pex * invT1));
        float bs = 0.0f;
#pragma unroll
        for (int j = 1; j < JW; ++j) {
            bs += g_logr[d0 - j];
            float Pj = Pex - bs;              // sum logr[0..d0-1-j]
            win[j] = pk2(wl0 * expf(Pj * invT0), wl1 * expf(Pj * invT1));
        }
    }
    u64 a = win[0];                            // A(d0-1)

    const u64 invT2 = pk2(invT0, invT1);
    const u64 ONE2  = pk2(1.0f, 1.0f);
    const u64 C2    = pk2(0.5f, 0.5f);
    const u64 C3    = pk2(1.0f / 6.0f, 1.0f / 6.0f);

    const float4* L4 = (const float4*)(g_logr + d0);
    u64* o = out + (size_t)d0 * npairs + p;

#define STEP(lrv) do {                                              \
        u64 m0 = mul2(pir[0], win[0]);                              \
        u64 m1 = mul2(pir[1], win[1]);                              \
        m0 = fma2(pir[2], win[2], m0);                              \
        m1 = fma2(pir[3], win[3], m1);                              \
        m0 = fma2(pir[4], win[4], m0);                              \
        m1 = fma2(pir[5], win[5], m1);                              \
        m0 = fma2(pir[6], win[6], m0);                              \
        m1 = fma2(pir[7], win[7], m1);                              \
        m0 = fma2(pir[8], win[8], m0);                              \
        m1 = fma2(pir[9], win[9], m1);                              \
        stcs64(o, add2(m0, m1));                                    \
        o += npairs;                                                \
        u64 x = mul2(pk2((lrv), (lrv)), invT2);                     \
        u64 e = fma2(x, fma2(x, fma2(x, C3, C2), ONE2), ONE2);      \
        a = mul2(a, e);                                             \
        _Pragma("unroll")                                           \
        for (int j = JW - 1; j > 0; --j) win[j] = win[j - 1];       \
        win[0] = a;                                                 \
    } while (0)

    // 25 iters of 4 days; unroll 5 -> 20 days/body = 2 full window rotations
#pragma unroll 5
    for (int it = 0; it < DCH / 4; ++it) {
        float4 L = L4[it];
        STEP(L.x);
        STEP(L.y);
        STEP(L.z);
        STEP(L.w);
    }
#undef STEP
}

extern "C" void kernel_launch(void* const* d_in, const int* in_sizes, int n_in,
                              void* d_out, int out_size) {
    const float* r    = (const float*)d_in[0];  // (1,T)
    const float* warm = (const float*)d_in[1];  // (J,S)
    const float* Ts   = (const float*)d_in[2];  // (S,)
    const float* rho  = (const float*)d_in[3];  // (S,)
    const float* pi   = (const float*)d_in[4];  // (J,S)

    int T = in_sizes[0];
    int S = in_sizes[2];
    int nch = (T + DCH - 1) / DCH;

    prep_kernel<<<1, 1024>>>(r, T, nch);

    int npairs = S / 2;
    dim3 grid((npairs + 127) / 128, nch);
    main_kernel<<<grid, 128>>>(warm, Ts, rho, pi, (u64*)d_out, T, S);
}

// round 4
// speedup vs baseline: 1.2153x; 1.2153x over previous
#include <cuda_runtime.h>
#include <math.h>

#define JW 10
#define DCH 50           // days per chunk (T=50000 -> 1000 chunks)
#define MAXCH 1024

// Scratch (allocation-free rule: __device__ globals)
__device__ double g_csum[MAXCH];
__device__ float  g_Pex[MAXCH];   // exclusive prefix of log r at chunk starts

typedef unsigned long long u64;

// ---- packed f32x2 helpers (sm_103a) ----
__device__ __forceinline__ u64 pk2(float lo, float hi) {
    u64 r; asm("mov.b64 %0, {%1, %2};" : "=l"(r) : "f"(lo), "f"(hi)); return r;
}
__device__ __forceinline__ u64 mul2(u64 a, u64 b) {
    u64 d; asm("mul.rn.f32x2 %0, %1, %2;" : "=l"(d) : "l"(a), "l"(b)); return d;
}
__device__ __forceinline__ u64 fma2(u64 a, u64 b, u64 c) {
    u64 d; asm("fma.rn.f32x2 %0, %1, %2, %3;" : "=l"(d) : "l"(a), "l"(b), "l"(c)); return d;
}
__device__ __forceinline__ u64 add2(u64 a, u64 b) {
    u64 d; asm("add.rn.f32x2 %0, %1, %2;" : "=l"(d) : "l"(a), "l"(b)); return d;
}
__device__ __forceinline__ void stcs64(u64* p, u64 v) {
    asm volatile("st.global.cs.b64 [%0], %1;" :: "l"(p), "l"(v) : "memory");
}

// log(1+x), |x| <= ~0.011: degree-5 poly, abs err ~1e-9 (used only for anchors)
__device__ __forceinline__ float log1p_poly(float x) {
    float p = fmaf(x, 0.2f, -0.25f);
    p = fmaf(x, p, 1.0f / 3.0f);
    p = fmaf(x, p, -0.5f);
    p = fmaf(x, p, 1.0f);
    return x * p;
}

// ---- kernel 1: per-chunk log-sum (one warp per chunk, double accum) ----
__global__ void __launch_bounds__(32) csum_kernel(const float* __restrict__ r, int T) {
    int c = blockIdx.x;
    int t = threadIdx.x;
    int base = c * DCH;
    double acc = 0.0;
    int i = base + 2 * t;
    if (2 * t < DCH) {
        if (i + 1 < T) {
            float2 rv = *(const float2*)(r + i);   // base is 200B-aligned
            acc = (double)log1p_poly(rv.x - 1.0f) + (double)log1p_poly(rv.y - 1.0f);
        } else if (i < T) {
            acc = (double)log1p_poly(r[i] - 1.0f);
        }
    }
#pragma unroll
    for (int off = 16; off > 0; off >>= 1)
        acc += __shfl_down_sync(0xffffffffu, acc, off);
    if (t == 0) g_csum[c] = acc;
}

// ---- kernel 2: exclusive scan of chunk sums (one block) ----
__global__ void __launch_bounds__(1024) scan_kernel(int nch) {
    __shared__ double sh[1024];
    int t = threadIdx.x;
    double v = (t < nch) ? g_csum[t] : 0.0;
    sh[t] = v;
    __syncthreads();
#pragma unroll
    for (int off = 1; off < 1024; off <<= 1) {
        double u = (t >= off) ? sh[t - off] : 0.0;
        __syncthreads();
        sh[t] += u;
        __syncthreads();
    }
    if (t < nch) g_Pex[t] = (float)(sh[t] - v);   // sum log r[0 .. t*DCH-1]
}

// ---- main kernel ----
// A[d,s] = wlast[s]*exp(P[d]*invT[s]); chunk anchored exactly via g_Pex + __expf.
// Day multiplier computed directly from r: (1+v)^t ~= 1 + t v + t(t-1)/2 v^2.
// Window init walks BACKWARD from the anchor with (1+v)^(-t) (degree-3).
// M[d,s] = sum_j (rho*pi[j,s]) * A_ext[J+d-1-j, s]
__global__ void __launch_bounds__(128) main_kernel(
    const float* __restrict__ r,      // (T,)
    const float* __restrict__ warm,   // (J,S)
    const float* __restrict__ Ts,     // (S,)
    const float* __restrict__ rho,    // (S,)
    const float* __restrict__ pi,     // (J,S)
    u64* __restrict__ out,            // (T, S/2) packed float2
    int T, int S)
{
    int p = blockIdx.x * blockDim.x + threadIdx.x;
    int npairs = S >> 1;
    if (p >= npairs) return;
    int c  = blockIdx.y;
    int d0 = c * DCH;
    int s0 = 2 * p;

    float t0 = 1.0f / Ts[s0];
    float t1 = 1.0f / Ts[s0 + 1];
    float rho0 = rho[s0], rho1 = rho[s0 + 1];

    // dot weights with rho folded in
    u64 pir[JW];
#pragma unroll
    for (int j = 0; j < JW; ++j)
        pir[j] = pk2(pi[j * S + s0] * rho0, pi[j * S + s0 + 1] * rho1);

    // forward step coefs: (1+v)^t ~= 1 + c1 v + c2 v^2
    const u64 C1  = pk2(t0, t1);
    const u64 C2  = pk2(0.5f * t0 * (t0 - 1.0f), 0.5f * t1 * (t1 - 1.0f));
    const u64 ONE2 = pk2(1.0f, 1.0f);

    // window init: win[j] = A_ext[J + d0 - 1 - j]
    u64 win[JW];
    if (c == 0) {
#pragma unroll
        for (int j = 0; j < JW; ++j)
            win[j] = pk2(warm[(JW - 1 - j) * S + s0],
                         warm[(JW - 1 - j) * S + s0 + 1]);
    } else {
        float wl0 = warm[(JW - 1) * S + s0];
        float wl1 = warm[(JW - 1) * S + s0 + 1];
        float Pex = g_Pex[c];                 // sum log r[0..d0-1]
        win[0] = pk2(wl0 * __expf(Pex * t0), wl1 * __expf(Pex * t1));
        // backward coefs: (1+v)^(-t) ~= 1 - t v + t(t+1)/2 v^2 - t(t+1)(t+2)/6 v^3
        u64 B1 = pk2(-t0, -t1);
        u64 B2 = pk2(0.5f * t0 * (t0 + 1.0f), 0.5f * t1 * (t1 + 1.0f));
        u64 B3 = pk2(-t0 * (t0 + 1.0f) * (t0 + 2.0f) / 6.0f,
                     -t1 * (t1 + 1.0f) * (t1 + 2.0f) / 6.0f);
#pragma unroll
        for (int j = 1; j < JW; ++j) {
            float v = r[d0 - j] - 1.0f;       // L2-hit scalar load
            u64 v2 = pk2(v, v);
            u64 e = fma2(v2, fma2(v2, fma2(v2, B3, B2), B1), ONE2);
            win[j] = mul2(win[j - 1], e);
        }
    }
    u64 a = win[0];                            // A(d0-1)

    const float2* R2 = (const float2*)(r + d0);   // d0*4B is 200B-aligned
    u64* o = out + (size_t)d0 * npairs + p;

#define STEP(rv) do {                                               \
        u64 m0 = mul2(pir[0], win[0]);                              \
        u64 m1 = mul2(pir[1], win[1]);                              \
        m0 = fma2(pir[2], win[2], m0);                              \
        m1 = fma2(pir[3], win[3], m1);                              \
        m0 = fma2(pir[4], win[4], m0);                              \
        m1 = fma2(pir[5], win[5], m1);                              \
        m0 = fma2(pir[6], win[6], m0);                              \
        m1 = fma2(pir[7], win[7], m1);                              \
        m0 = fma2(pir[8], win[8], m0);                              \
        m1 = fma2(pir[9], win[9], m1);                              \
        stcs64(o, add2(m0, m1));                                    \
        o += npairs;                                                \
        float vv = (rv) - 1.0f;                                     \
        u64 v2 = pk2(vv, vv);                                       \
        u64 e = fma2(v2, fma2(v2, C2, C1), ONE2);                   \
        a = mul2(a, e);                                             \
        _Pragma("unroll")                                           \
        for (int j = JW - 1; j > 0; --j) win[j] = win[j - 1];       \
        win[0] = a;                                                 \
    } while (0)

    if (d0 + DCH <= T) {
        // 25 iters of 2 days; unroll 5 -> 10 days/body = 1 full window rotation
#pragma unroll 5
        for (int it = 0; it < DCH / 2; ++it) {
            float2 L = R2[it];
            STEP(L.x);
            STEP(L.y);
        }
    } else {
        for (int d = d0; d < T; ++d) {
            float rv = r[d];
            STEP(rv);
        }
    }
#undef STEP
}

extern "C" void kernel_launch(void* const* d_in, const int* in_sizes, int n_in,
                              void* d_out, int out_size) {
    const float* r    = (const float*)d_in[0];  // (1,T)
    const float* warm = (const float*)d_in[1];  // (J,S)
    const float* Ts   = (const float*)d_in[2];  // (S,)
    const float* rho  = (const float*)d_in[3];  // (S,)
    const float* pi   = (const float*)d_in[4];  // (J,S)

    int T = in_sizes[0];
    int S = in_sizes[2];
    int nch = (T + DCH - 1) / DCH;

    csum_kernel<<<nch, 32>>>(r, T);
    scan_kernel<<<1, 1024>>>(nch);

    int npairs = S / 2;
    dim3 grid((npairs + 127) / 128, nch);
    main_kernel<<<grid, 128>>>(r, warm, Ts, rho, pi, (u64*)d_out, T, S);
}

// round 5
// speedup vs baseline: 2.0238x; 1.6653x over previous
#include <cuda_runtime.h>
#include <math.h>

#define JW 10
#define DCH 100          // days per chunk (T=50000 -> 500 chunks)
#define MAXCH 1024

// Scratch (allocation-free rule: __device__ globals)
__device__ double g_csum[MAXCH];
__device__ float  g_Pex[MAXCH];   // exclusive prefix of log r at chunk starts

typedef unsigned long long u64;

// ---- packed f32x2 helpers (sm_103a) ----
__device__ __forceinline__ u64 pk2(float lo, float hi) {
    u64 r; asm("mov.b64 %0, {%1, %2};" : "=l"(r) : "f"(lo), "f"(hi)); return r;
}
__device__ __forceinline__ u64 mul2(u64 a, u64 b) {
    u64 d; asm("mul.rn.f32x2 %0, %1, %2;" : "=l"(d) : "l"(a), "l"(b)); return d;
}
__device__ __forceinline__ u64 fma2(u64 a, u64 b, u64 c) {
    u64 d; asm("fma.rn.f32x2 %0, %1, %2, %3;" : "=l"(d) : "l"(a), "l"(b), "l"(c)); return d;
}
__device__ __forceinline__ u64 add2(u64 a, u64 b) {
    u64 d; asm("add.rn.f32x2 %0, %1, %2;" : "=l"(d) : "l"(a), "l"(b)); return d;
}
__device__ __forceinline__ void stcs64(u64* p, u64 v) {
    asm volatile("st.global.cs.b64 [%0], %1;" :: "l"(p), "l"(v) : "memory");
}

// log(1+x), |x| <= ~0.011: degree-5 poly, abs err ~1e-9
__device__ __forceinline__ float log1p_poly(float x) {
    float p = fmaf(x, 0.2f, -0.25f);
    p = fmaf(x, p, 1.0f / 3.0f);
    p = fmaf(x, p, -0.5f);
    p = fmaf(x, p, 1.0f);
    return x * p;
}

// ---- kernel 1: per-chunk log-sum (one warp per chunk, double accum) ----
// Each thread handles 4 days (2 float2 loads); 25 of 32 lanes active.
__global__ void __launch_bounds__(32) csum_kernel(const float* __restrict__ r, int T) {
    int c = blockIdx.x;
    int t = threadIdx.x;
    int base = c * DCH + 4 * t;
    double acc = 0.0;
    if (4 * t < DCH) {
#pragma unroll
        for (int k = 0; k < 2; ++k) {
            int i = base + 2 * k;
            if (i + 1 < T) {
                float2 rv = *(const float2*)(r + i);   // chunk base 400B-aligned
                acc += (double)log1p_poly(rv.x - 1.0f)
                     + (double)log1p_poly(rv.y - 1.0f);
            } else if (i < T) {
                acc += (double)log1p_poly(r[i] - 1.0f);
            }
        }
    }
#pragma unroll
    for (int off = 16; off > 0; off >>= 1)
        acc += __shfl_down_sync(0xffffffffu, acc, off);
    if (t == 0) g_csum[c] = acc;
}

// ---- kernel 2: exclusive scan of chunk sums (one block, <=512 chunks) ----
__global__ void __launch_bounds__(512) scan_kernel(int nch) {
    __shared__ double sh[512];
    int t = threadIdx.x;
    double v = (t < nch) ? g_csum[t] : 0.0;
    sh[t] = v;
    __syncthreads();
#pragma unroll
    for (int off = 1; off < 512; off <<= 1) {
        double u = (t >= off) ? sh[t - off] : 0.0;
        __syncthreads();
        sh[t] += u;
        __syncthreads();
    }
    if (t < nch) g_Pex[t] = (float)(sh[t] - v);   // sum log r[0 .. t*DCH-1]
}

// ---- main kernel ----
// A[d,s] = wlast[s]*exp(P[d]*invT[s]); chunk + window anchored via g_Pex and
// per-day log1p corrections, evaluated with __expf (independent, latency-flat).
// Day multiplier from r directly: (1+v)^t ~= 1 + t v + t(t-1)/2 v^2.
// M[d,s] = sum_j (rho*pi[j,s]) * A_ext[J+d-1-j, s]
__global__ void __launch_bounds__(128) main_kernel(
    const float* __restrict__ r,      // (T,)
    const float* __restrict__ warm,   // (J,S)
    const float* __restrict__ Ts,     // (S,)
    const float* __restrict__ rho,    // (S,)
    const float* __restrict__ pi,     // (J,S)
    u64* __restrict__ out,            // (T, S/2) packed float2
    int T, int S)
{
    int p = blockIdx.x * blockDim.x + threadIdx.x;
    int npairs = S >> 1;
    if (p >= npairs) return;
    int c  = blockIdx.y;
    int d0 = c * DCH;
    int s0 = 2 * p;

    float t0 = 1.0f / Ts[s0];
    float t1 = 1.0f / Ts[s0 + 1];
    float rho0 = rho[s0], rho1 = rho[s0 + 1];

    // dot weights with rho folded in
    u64 pir[JW];
#pragma unroll
    for (int j = 0; j < JW; ++j)
        pir[j] = pk2(pi[j * S + s0] * rho0, pi[j * S + s0 + 1] * rho1);

    // forward step coefs: (1+v)^t ~= 1 + c1 v + c2 v^2
    const u64 C1   = pk2(t0, t1);
    const u64 C2   = pk2(0.5f * t0 * (t0 - 1.0f), 0.5f * t1 * (t1 - 1.0f));
    const u64 ONE2 = pk2(1.0f, 1.0f);

    // window init: win[j] = A_ext[J + d0 - 1 - j]
    u64 win[JW];
    if (c == 0) {
#pragma unroll
        for (int j = 0; j < JW; ++j)
            win[j] = pk2(warm[(JW - 1 - j) * S + s0],
                         warm[(JW - 1 - j) * S + s0 + 1]);
    } else {
        float wl0 = warm[(JW - 1) * S + s0];
        float wl1 = warm[(JW - 1) * S + s0 + 1];
        // P values at the 10 window positions: independent exp evaluations
        float Pj = g_Pex[c];                  // sum log r[0..d0-1]
        win[0] = pk2(wl0 * __expf(Pj * t0), wl1 * __expf(Pj * t1));
#pragma unroll
        for (int j = 1; j < JW; ++j) {
            Pj -= log1p_poly(r[d0 - j] - 1.0f);   // scalar adds, loads indep
            win[j] = pk2(wl0 * __expf(Pj * t0), wl1 * __expf(Pj * t1));
        }
    }
    u64 a = win[0];                            // A(d0-1)

    const float4* R4 = (const float4*)(r + d0);   // d0*4B is 400B-aligned
    u64* o = out + (size_t)d0 * npairs + p;

#define STEP(rv) do {                                               \
        u64 m0 = mul2(pir[0], win[0]);                              \
        u64 m1 = mul2(pir[1], win[1]);                              \
        m0 = fma2(pir[2], win[2], m0);                              \
        m1 = fma2(pir[3], win[3], m1);                              \
        m0 = fma2(pir[4], win[4], m0);                              \
        m1 = fma2(pir[5], win[5], m1);                              \
        m0 = fma2(pir[6], win[6], m0);                              \
        m1 = fma2(pir[7], win[7], m1);                              \
        m0 = fma2(pir[8], win[8], m0);                              \
        m1 = fma2(pir[9], win[9], m1);                              \
        stcs64(o, add2(m0, m1));                                    \
        o += npairs;                                                \
        float vv = (rv) - 1.0f;                                     \
        u64 v2 = pk2(vv, vv);                                       \
        u64 e = fma2(v2, fma2(v2, C2, C1), ONE2);                   \
        a = mul2(a, e);                                             \
        _Pragma("unroll")                                           \
        for (int j = JW - 1; j > 0; --j) win[j] = win[j - 1];       \
        win[0] = a;                                                 \
    } while (0)

    if (d0 + DCH <= T) {
        // 25 iters of 4 days; unroll 5 -> 20 days/body = 2 full window rotations
#pragma unroll 5
        for (int it = 0; it < DCH / 4; ++it) {
            float4 L = R4[it];
            STEP(L.x);
            STEP(L.y);
            STEP(L.z);
            STEP(L.w);
        }
    } else {
        for (int d = d0; d < T; ++d) {
            float rv = r[d];
            STEP(rv);
        }
    }
#undef STEP
}

extern "C" void kernel_launch(void* const* d_in, const int* in_sizes, int n_in,
                              void* d_out, int out_size) {
    const float* r    = (const float*)d_in[0];  // (1,T)
    const float* warm = (const float*)d_in[1];  // (J,S)
    const float* Ts   = (const float*)d_in[2];  // (S,)
    const float* rho  = (const float*)d_in[3];  // (S,)
    const float* pi   = (const float*)d_in[4];  // (J,S)

    int T = in_sizes[0];
    int S = in_sizes[2];
    int nch = (T + DCH - 1) / DCH;

    csum_kernel<<<nch, 32>>>(r, T);
    scan_kernel<<<1, 512>>>(nch);

    int npairs = S / 2;
    dim3 grid((npairs + 127) / 128, nch);
    main_kernel<<<grid, 128>>>(r, warm, Ts, rho, pi, (u64*)d_out, T, S);
}